// round 13
// baseline (speedup 1.0000x reference)
#include <cuda_runtime.h>

// Problem constants
#define BF_TOT  (16 * 4096)      // B * F = 65536
#define PAIRS   6                // 12 data symbols -> 6 STBC pairs
#define NBITS0  3145728          // BF_TOT * 48
#define NGAIN   786432           // BF_TOT * 12
#define N_ITER  8                // pairs per warp-slot (pipelined)
#define THREADS 256
#define SMEM_BYTES (2 * 8 * 256 * 16)   // double-buffered stash, 64 KB

typedef unsigned long long u64;

// ---- packed f32x2 primitives (sm_103a) ----
__device__ __forceinline__ u64 pk(float lo, float hi){
    u64 r; asm("mov.b64 %0, {%1, %2};" : "=l"(r) : "f"(lo), "f"(hi)); return r;
}
__device__ __forceinline__ void unpk(u64 v, float& lo, float& hi){
    asm("mov.b64 {%0, %1}, %2;" : "=f"(lo), "=f"(hi) : "l"(v));
}
__device__ __forceinline__ float usum(u64 v){ float lo, hi; unpk(v, lo, hi); return lo + hi; }
__device__ __forceinline__ u64 fmul2(u64 a, u64 b){
    u64 d; asm("mul.rn.f32x2 %0, %1, %2;" : "=l"(d) : "l"(a), "l"(b)); return d;
}
__device__ __forceinline__ u64 fadd2(u64 a, u64 b){
    u64 d; asm("add.rn.f32x2 %0, %1, %2;" : "=l"(d) : "l"(a), "l"(b)); return d;
}
__device__ __forceinline__ u64 fsub2(u64 a, u64 b){
    u64 d; asm("sub.rn.f32x2 %0, %1, %2;" : "=l"(d) : "l"(a), "l"(b)); return d;
}
__device__ __forceinline__ u64 ffma2(u64 a, u64 b, u64 c){
    u64 d; asm("fma.rn.f32x2 %0, %1, %2, %3;" : "=l"(d) : "l"(a), "l"(b), "l"(c)); return d;
}
__device__ __forceinline__ u64 dot2(u64 a, u64 b, u64 c, u64 d){
    return ffma2(c, d, fmul2(a, b));
}
__device__ __forceinline__ u64 dot4(u64 a,u64 b,u64 c,u64 d,u64 e,u64 f,u64 g,u64 h){
    return ffma2(g, h, ffma2(e, f, ffma2(c, d, fmul2(a, b))));
}

// ---- cp.async (LDGSTS) ----
__device__ __forceinline__ void cp16(unsigned dst, const void* src){
    asm volatile("cp.async.cg.shared.global [%0], [%1], 16;" :: "r"(dst), "l"(src) : "memory");
}
__device__ __forceinline__ void cp_commit(){ asm volatile("cp.async.commit_group;" ::: "memory"); }
template<int N> __device__ __forceinline__ void cp_wait(){
    asm volatile("cp.async.wait_group %0;" :: "n"(N) : "memory");
}

// ---- scalar complex helpers (solve path) ----
__device__ __forceinline__ float2 cmul (float2 a, float2 b){ return make_float2(a.x*b.x - a.y*b.y, a.x*b.y + a.y*b.x); }
__device__ __forceinline__ float2 cmulc(float2 a, float2 b){ return make_float2(a.x*b.x + a.y*b.y, a.x*b.y - a.y*b.x); }
__device__ __forceinline__ float2 cadd (float2 a, float2 b){ return make_float2(a.x+b.x, a.y+b.y); }
__device__ __forceinline__ float2 csub (float2 a, float2 b){ return make_float2(a.x-b.x, a.y-b.y); }
__device__ __forceinline__ float2 cscl (float2 a, float s){ return make_float2(a.x*s, a.y*s); }
__device__ __forceinline__ float2 cconj(float2 a){ return make_float2(a.x, -a.y); }

// 16-QAM Gray hard decision with configurable magnitude threshold.
__device__ __forceinline__ void hd16(float2 y, float thr, float2& pt, int& bits){
    const float C1 = 0.31622776601683794f;   // 1/sqrt(10)
    const float C3 = 0.9486832980505138f;    // 3/sqrt(10)
    int b0 = (y.x < 0.0f);
    int b1 = (y.y < 0.0f);
    int b2 = (fabsf(y.x) > thr);
    int b3 = (fabsf(y.y) > thr);
    float xi = b2 ? C3 : C1; if (b0) xi = -xi;
    float xq = b3 ? C3 : C1; if (b1) xq = -xq;
    pt = make_float2(xi, xq);
    bits = b0 | (b1 << 1) | (b2 << 2) | (b3 << 3);
}

// 3-step xor butterfly over each 8-lane group (result broadcast within group)
#define RED8(v) do { \
    v += __shfl_xor_sync(0xffffffffu, v, 1);  \
    v += __shfl_xor_sync(0xffffffffu, v, 2);  \
    v += __shfl_xor_sync(0xffffffffu, v, 4);  \
} while (0)

// Full per-pair computation (identical math to the 96.7us kernel).
// sp = this thread's slot-0 element in the active buffer (slot stride 256).
__device__ __forceinline__ void process_pair(float4* __restrict__ sp,
    const float2* __restrict__ y, unsigned P, int j, float* __restrict__ out)
{
    const unsigned bf = P / PAIRS;
    const unsigned p  = P - bf * PAIRS;

    // ---- raw channel from smem (cp.async landed here) ----
    float4 hrA0 = sp[0],    hiA0 = sp[256];
    float4 hrB0 = sp[512],  hiB0 = sp[768];
    float4 hrA1 = sp[1024], hiA1 = sp[1280];
    float4 hrB1 = sp[1536], hiB1 = sp[1792];

    // ---- pack per-antenna pairs: (antenna j, antenna j+8) as f32x2 ----
    u64 pAaR = pk(hrA0.x, hrA1.x), pAaI = pk(hiA0.x, hiA1.x);
    u64 pAbR = pk(hrA0.y, hrA1.y), pAbI = pk(hiA0.y, hiA1.y);
    u64 pAcR = pk(hrA0.z, hrA1.z), pAcI = pk(hiA0.z, hiA1.z);
    u64 pAdR = pk(hrA0.w, hrA1.w), pAdI = pk(hiA0.w, hiA1.w);
    u64 pBaR = pk(hrB0.x, hrB1.x), pBaI = pk(hiB0.x, hiB1.x);
    u64 pBbR = pk(hrB0.y, hrB1.y), pBbI = pk(hiB0.y, hiB1.y);
    u64 pBcR = pk(hrB0.z, hrB1.z), pBcI = pk(hiB0.z, hiB1.z);
    u64 pBdR = pk(hrB0.w, hrB1.w), pBdI = pk(hiB0.w, hiB1.w);

    // overwrite the stash in packed layout for the SIC pass (same thread,
    // same addresses -> program-order safe; prefetch targets the OTHER buffer)
    ulonglong2* up = (ulonglong2*)sp;
    up[0]    = make_ulonglong2(pAaR, pAaI);
    up[256]  = make_ulonglong2(pAbR, pAbI);
    up[512]  = make_ulonglong2(pAcR, pAcI);
    up[768]  = make_ulonglong2(pAdR, pAdI);
    up[1024] = make_ulonglong2(pBaR, pBaI);
    up[1280] = make_ulonglong2(pBbR, pBbI);
    up[1536] = make_ulonglong2(pBcR, pBcI);
    up[1792] = make_ulonglong2(pBdR, pBdI);

    // summed channel (2x average; scale folded into thresholds/invG/gains)
    u64 aR = fadd2(pAaR, pBaR), aI = fadd2(pAaI, pBaI);
    u64 bR = fadd2(pAbR, pBbR), bI = fadd2(pAbI, pBbI);
    u64 cR = fadd2(pAcR, pBcR), cI = fadd2(pAcI, pBcI);
    u64 dR = fadd2(pAdR, pBdR), dI = fadd2(pAdI, pBdI);

    u64 yAr = pk(y[0].x, y[1].x), yAi = pk(y[0].y, y[1].y);
    u64 yBr = pk(y[2].x, y[3].x), yBi = pk(y[2].y, y[3].y);

    // ---- packed Gram/rhs (both antennas at once), unpack to scalars ----
    float alpha = usum(dot4(aR,aR, aI,aI, bR,bR, bI,bI));
    float beta  = usum(dot4(cR,cR, cI,cI, dR,dR, dI,dI));
    float2 gam, del, u0, u1, u2, u3;
    gam.x = usum(dot4(aR,cR, aI,cI, bR,dR, bI,dI));
    gam.y = usum(fsub2(dot2(aR,cI, bI,dR), dot2(aI,cR, bR,dI)));
    del.x = usum(fsub2(dot2(aR,dR, aI,dI), dot2(bR,cR, bI,cI)));
    del.y = usum(fsub2(dot2(aR,dI, bR,cI), dot2(aI,dR, bI,cR)));
    u0.x  = usum(dot4(aR,yAr, aI,yAi, bR,yBr, bI,yBi));
    u0.y  = usum(fsub2(dot2(aR,yAi, bI,yBr), dot2(aI,yAr, bR,yBi)));
    u1.x  = usum(fsub2(dot2(bR,yAr, bI,yAi), dot2(aR,yBr, aI,yBi)));
    u1.y  = usum(fsub2(dot2(bR,yAi, aR,yBi), dot2(bI,yAr, aI,yBr)));
    u2.x  = usum(dot4(cR,yAr, cI,yAi, dR,yBr, dI,yBi));
    u2.y  = usum(fsub2(dot2(cR,yAi, dI,yBr), dot2(cI,yAr, dR,yBi)));
    u3.x  = usum(fsub2(dot2(dR,yAr, dI,yAi), dot2(cR,yBr, cI,yBi)));
    u3.y  = usum(fsub2(dot2(dR,yAi, cR,yBi), dot2(dI,yAr, cI,yBr)));

    // ---- 8-lane reductions (broadcast within pair group) ----
    RED8(alpha); RED8(beta);
    RED8(gam.x); RED8(gam.y); RED8(del.x); RED8(del.y);
    RED8(u0.x);  RED8(u0.y);  RED8(u1.x);  RED8(u1.y);
    RED8(u2.x);  RED8(u2.y);  RED8(u3.x);  RED8(u3.y);

    // ---- closed-form Schur solve (scaled: Ghat=4G, uhat=2u -> shat=s/2) ----
    const float e      = gam.x*gam.x + gam.y*gam.y + del.x*del.x + del.y*del.y;
    const float invden = 1.0f / (alpha * beta - e);
    const float invA   = 1.0f / alpha;
    float2 t2 = csub(cscl(u2, alpha), csub(cmulc(gam, u0), cmul(del, u1)));
    float2 t3 = csub(cscl(u3, alpha), cadd(cmulc(del, u0), cmul(gam, u1)));
    float2 s2 = cscl(t2, invden);
    float2 s3 = cscl(t3, invden);
    float2 s0 = cscl(csub(u0, cadd(cmul(gam, s2), cmul(del, s3))), invA);
    float2 s1 = cscl(cadd(u1, csub(cmul(cconj(del), s2), cmul(cconj(gam), s3))), invA);

    const bool c0 = (alpha >= beta);

    const float THALF = 0.31622776601683794f;   // (2/sqrt(10)) / 2
    const float TFULL = 0.6324555320336759f;    //  2/sqrt(10)
    float2 px0, px1, px2, px3; int ib0, ib1, ib2, ib3;
    hd16(s0, THALF, px0, ib0); hd16(s1, THALF, px1, ib1);
    hd16(s2, THALF, px2, ib2); hd16(s3, THALF, px3, ib3);

    float2 bx0 = c0 ? px0 : px2;     // better-stream decisions (sym A, sym B)
    float2 bx1 = c0 ? px1 : px3;

    u64 B0R = pk(bx0.x, bx0.x), B0I = pk(bx0.y, bx0.y);
    u64 B1R = pk(bx1.x, bx1.x), B1I = pk(bx1.y, bx1.y);

    // ---- SIC (packed): reload packed channel from smem ----
    ulonglong2 cbA0 = up[(c0 ? 0 : 2)*256];
    ulonglong2 cbA1 = up[(c0 ? 1 : 3)*256];
    ulonglong2 cbB0 = up[(c0 ? 4 : 6)*256];
    ulonglong2 cbB1 = up[(c0 ? 5 : 7)*256];
    ulonglong2 wA0  = up[(c0 ? 2 : 0)*256];
    ulonglong2 wA1  = up[(c0 ? 3 : 1)*256];
    ulonglong2 wB0  = up[(c0 ? 6 : 4)*256];
    ulonglong2 wB1  = up[(c0 ? 7 : 5)*256];
    u64 g0R = fadd2(wA0.x, wB0.x), g0I = fadd2(wA0.y, wB0.y);
    u64 g1R = fadd2(wA1.x, wB1.x), g1I = fadd2(wA1.y, wB1.y);

    // eA = cbA0*bx0 + cbA1*bx1
    u64 eAr = fsub2(dot2(cbA0.x,B0R, cbA1.x,B1R), dot2(cbA0.y,B0I, cbA1.y,B1I));
    u64 eAi = dot4(cbA0.x,B0I, cbA0.y,B0R, cbA1.x,B1I, cbA1.y,B1R);
    // eB = cbB0*(-conj(bx1)) + cbB1*conj(bx0)
    u64 eBr = fsub2(dot2(cbB1.x,B0R, cbB1.y,B0I), dot2(cbB0.x,B1R, cbB0.y,B1I));
    u64 eBi = fsub2(dot2(cbB0.x,B1I, cbB1.y,B0R), dot2(cbB0.y,B1R, cbB1.x,B0I));
    u64 rnAr = fsub2(yAr, eAr), rnAi = fsub2(yAi, eAi);
    u64 rnBr = fsub2(yBr, eBr), rnBi = fsub2(yBi, eBi);

    // t0 = conj(g0)*rnA + g1*conj(rnB); t1 = conj(g1)*rnA - g0*conj(rnB)
    float2 t0, t1;
    t0.x = usum(dot4(g0R,rnAr, g0I,rnAi, g1R,rnBr, g1I,rnBi));
    t0.y = usum(fsub2(dot2(g0R,rnAi, g1I,rnBr), dot2(g0I,rnAr, g1R,rnBi)));
    t1.x = usum(fsub2(dot2(g1R,rnAr, g1I,rnAi), dot2(g0R,rnBr, g0I,rnBi)));
    t1.y = usum(fsub2(dot2(g1R,rnAi, g0R,rnBi), dot2(g1I,rnAr, g0I,rnBr)));
    RED8(t0.x); RED8(t0.y); RED8(t1.x); RED8(t1.y);

    const float invG = 2.0f / (c0 ? beta : alpha);
    float2 pn0, pn1; int ibn0, ibn1;
    hd16(cscl(t0, invG), TFULL, pn0, ibn0);
    hd16(cscl(t1, invG), TFULL, pn1, ibn1);

    const int bb0 = c0 ? ib0 : ib2;
    const int bb1 = c0 ? ib1 : ib3;
    const int b0A = c0 ? bb0  : ibn0;
    const int b0B = c0 ? bb1  : ibn1;
    const int b1A = c0 ? ibn0 : bb0;
    const int b1B = c0 ? ibn1 : bb1;

    float* bits0 = out;
    float* bits1 = out + NBITS0;
    float* g0out = out + 2 * NBITS0;
    float* g1out = out + 2 * NBITS0 + NGAIN;

    const unsigned sym0 = 2u * p;
    const unsigned bbase = bf*48u + sym0*4u;     // float4-aligned

    if (j < 4) {
        int nib = (j == 0) ? b0A : (j == 1) ? b0B : (j == 2) ? b1A : b1B;
        float4 v = make_float4((float)( nib       & 1), (float)((nib >> 1) & 1),
                               (float)((nib >> 2) & 1), (float)((nib >> 3) & 1));
        float* base = (j < 2) ? bits0 : bits1;
        *(float4*)(base + bbase + ((j & 1) << 2)) = v;
    } else if (j == 4) {
        float g = alpha * 0.25f;
        *(float2*)(g0out + bf*12u + sym0) = make_float2(g, g);
    } else if (j == 5) {
        float g = beta * 0.25f;
        *(float2*)(g1out + bf*12u + sym0) = make_float2(g, g);
    }
}

__global__ void __launch_bounds__(THREADS, 3)
mc_ncjt_kernel(const float* __restrict__ ryR, const float* __restrict__ ryI,
               const float* __restrict__ hR,  const float* __restrict__ hI,
               float* __restrict__ out)
{
    extern __shared__ float4 smbuf[];   // [2 buffers][8 slots][256 threads]

    const int tid  = threadIdx.x;
    const int lane = tid & 31;
    const int q    = lane >> 3;       // pair within warp (4 pairs concurrent)
    const int j    = lane & 7;        // lane owns antennas j and j+8

    const unsigned wglob = blockIdx.x * (THREADS/32) + (unsigned)(tid >> 5);
    const float4* hR4 = (const float4*)hR;
    const float4* hI4 = (const float4*)hI;

    const unsigned smem0 = (unsigned)__cvta_generic_to_shared(smbuf) + (unsigned)tid * 16u;

    unsigned Pcur = wglob * (4u * N_ITER) + (unsigned)q;

    // ---- prologue: prefetch iteration 0 ----
    float2 ycur[4];
    {
        unsigned bf = Pcur / PAIRS, pp = Pcur - bf * PAIRS;
        unsigned sA = 2u*pp + (pp>=1u) + (pp>=5u);
        unsigned rb = bf * 224u;
        unsigned iA = rb + sA*16u + (unsigned)j, iB = iA + 16u;
        cp16(smem0 +     0, hR4 + iA);     cp16(smem0 +  4096, hI4 + iA);
        cp16(smem0 +  8192, hR4 + iB);     cp16(smem0 + 12288, hI4 + iB);
        cp16(smem0 + 16384, hR4 + iA + 8); cp16(smem0 + 20480, hI4 + iA + 8);
        cp16(smem0 + 24576, hR4 + iB + 8); cp16(smem0 + 28672, hI4 + iB + 8);
        cp_commit();
        ycur[0] = make_float2(__ldcs(ryR + iA),     __ldcs(ryI + iA));
        ycur[1] = make_float2(__ldcs(ryR + iA + 8), __ldcs(ryI + iA + 8));
        ycur[2] = make_float2(__ldcs(ryR + iB),     __ldcs(ryI + iB));
        ycur[3] = make_float2(__ldcs(ryR + iB + 8), __ldcs(ryI + iB + 8));
    }

    #pragma unroll 1
    for (int it = 0; it < N_ITER; ++it) {
        float2 ynext[4];
        if (it + 1 < N_ITER) {
            unsigned Pn = Pcur + 4u;
            unsigned bf = Pn / PAIRS, pp = Pn - bf * PAIRS;
            unsigned sA = 2u*pp + (pp>=1u) + (pp>=5u);
            unsigned rb = bf * 224u;
            unsigned iA = rb + sA*16u + (unsigned)j, iB = iA + 16u;
            unsigned d = smem0 + (unsigned)((it + 1) & 1) * 32768u;
            cp16(d +     0, hR4 + iA);     cp16(d +  4096, hI4 + iA);
            cp16(d +  8192, hR4 + iB);     cp16(d + 12288, hI4 + iB);
            cp16(d + 16384, hR4 + iA + 8); cp16(d + 20480, hI4 + iA + 8);
            cp16(d + 24576, hR4 + iB + 8); cp16(d + 28672, hI4 + iB + 8);
            cp_commit();
            ynext[0] = make_float2(__ldcs(ryR + iA),     __ldcs(ryI + iA));
            ynext[1] = make_float2(__ldcs(ryR + iA + 8), __ldcs(ryI + iA + 8));
            ynext[2] = make_float2(__ldcs(ryR + iB),     __ldcs(ryI + iB));
            ynext[3] = make_float2(__ldcs(ryR + iB + 8), __ldcs(ryI + iB + 8));
            cp_wait<1>();   // current iteration's tile is resident
        } else {
            ynext[0] = ynext[1] = ynext[2] = ynext[3] = make_float2(0.f, 0.f);
            cp_wait<0>();   // last tile
        }

        process_pair(smbuf + (it & 1) * 2048 + tid, ycur, Pcur, j, out);

        ycur[0] = ynext[0]; ycur[1] = ynext[1];
        ycur[2] = ynext[2]; ycur[3] = ynext[3];
        Pcur += 4u;
    }

    if (blockIdx.x == 0 && tid == 0)
        out[2 * (NBITS0 + NGAIN)] = 0.4f;    // nvar scalar
}

extern "C" void kernel_launch(void* const* d_in, const int* in_sizes, int n_in,
                              void* d_out, int out_size) {
    const float* ryR = (const float*)d_in[0];
    const float* ryI = (const float*)d_in[1];
    const float* hR  = (const float*)d_in[2];
    const float* hI  = (const float*)d_in[3];
    float* out = (float*)d_out;

    // dynamic smem opt-in (idempotent; safe under graph capture)
    cudaFuncSetAttribute(mc_ncjt_kernel,
                         cudaFuncAttributeMaxDynamicSharedMemorySize, SMEM_BYTES);

    // total pairs = 393216; 4 pairs/warp-iter, 8 warps, N_ITER iters -> 1536 blocks
    const int total_pairs = BF_TOT * PAIRS;
    const int blocks = total_pairs / (32 * N_ITER);
    mc_ncjt_kernel<<<blocks, THREADS, SMEM_BYTES>>>(ryR, ryI, hR, hI, out);
}